// round 15
// baseline (speedup 1.0000x reference)
#include <cuda_runtime.h>
#include <cuda_fp16.h>
#include <math.h>
#include <stdint.h>

#define Bv 1024
#define Hv 512
#define Gv 2048
#define Tv 64
#define FUT 64
#define BH (Bv*Hv)

// ---------------- static device scratch ----------------
__device__ __half  g_hbuf[2][3][BH];
__device__ float   g_cbuf[3][BH];
__device__ __half  g_x[Tv][BH];
__device__ __half  g_dout[FUT][BH];
__device__ __half  g_W[6][Gv*1024];
__device__ float   g_bsum[6][Gv];
__device__ __half  g_Wout[Hv*Hv];

struct Cell {
    const __half* inp; const __half* hprev; const __half* W;
    const float* bsum; float* cbuf; __half* hout;
};
struct Diag { Cell c[3]; };

// ---------------- helpers ----------------
__device__ __forceinline__ void cp16(void* s, const void* g){
    unsigned sa = (unsigned)__cvta_generic_to_shared(s);
    asm volatile("cp.async.cg.shared.global [%0], [%1], 16;\n" :: "r"(sa), "l"(g));
}
__device__ __forceinline__ void cp_commit(){
    asm volatile("cp.async.commit_group;\n" ::: "memory");
}
template<int N> __device__ __forceinline__ void cp_wait(){
    asm volatile("cp.async.wait_group %0;\n" :: "n"(N) : "memory");
}
__device__ __forceinline__ void mma16(float* c, const unsigned* a, const unsigned* b){
    asm volatile("mma.sync.aligned.m16n8k16.row.col.f32.f16.f16.f32 "
        "{%0,%1,%2,%3}, {%4,%5,%6,%7}, {%8,%9}, {%0,%1,%2,%3};\n"
        : "+f"(c[0]), "+f"(c[1]), "+f"(c[2]), "+f"(c[3])
        : "r"(a[0]), "r"(a[1]), "r"(a[2]), "r"(a[3]), "r"(b[0]), "r"(b[1]));
}
__device__ __forceinline__ void ldsm4(unsigned* r, uint32_t a){
    asm volatile("ldmatrix.sync.aligned.m8n8.x4.shared.b16 {%0,%1,%2,%3}, [%4];"
        : "=r"(r[0]), "=r"(r[1]), "=r"(r[2]), "=r"(r[3]) : "r"(a));
}
__device__ __forceinline__ float sigm(float x){ return 1.f/(1.f + __expf(-x)); }

// ---------------- prep kernels ----------------
__global__ void transpose_k(const float* __restrict__ in){
    __shared__ float tile[32][33];
    int b = blockIdx.z;
    int h0 = blockIdx.x*32, t0 = blockIdx.y*32;
    int tx = threadIdx.x, ty = threadIdx.y;
    tile[ty][tx] = in[((size_t)b*Hv + h0 + ty)*Tv + t0 + tx];
    __syncthreads();
    g_x[t0+ty][(size_t)b*Hv + h0 + tx] = __float2half(tile[tx][ty]);
}

__global__ void wconv_k(const float* __restrict__ eWih, const float* __restrict__ eWhh,
                        const float* __restrict__ ebih, const float* __restrict__ ebhh,
                        const float* __restrict__ dWih, const float* __restrict__ dWhh,
                        const float* __restrict__ dbih, const float* __restrict__ dbhh,
                        const float* __restrict__ oW){
    long long idx = (long long)blockIdx.x*256 + threadIdx.x;
    const long long N1 = 6LL*2048*1024;
    const long long N2 = 512LL*512;
    const long long N3 = 6LL*2048;
    if (idx < N1){
        int L   = (int)(idx >> 21);
        int rem = (int)(idx & ((1u<<21)-1));
        int j = rem >> 10, k = rem & 1023;
        int l = (L < 3) ? L : L - 3;
        const float* Wih = (L < 3) ? eWih : dWih;
        const float* Whh = (L < 3) ? eWhh : dWhh;
        float v = (k < 512) ? Wih[((size_t)l*2048 + j)*512 + k]
                            : Whh[((size_t)l*2048 + j)*512 + k - 512];
        ((__half*)g_W)[idx] = __float2half(v);
    } else if (idx < N1 + N2){
        int i2 = (int)(idx - N1);
        ((__half*)g_Wout)[i2] = __float2half(oW[i2]);
    } else if (idx < N1 + N2 + N3){
        int i3 = (int)(idx - N1 - N2);
        int L = i3 >> 11, j = i3 & 2047;
        int l = (L < 3) ? L : L - 3;
        ((float*)g_bsum)[i3] = ((L < 3) ? ebih : dbih)[l*2048 + j]
                             + ((L < 3) ? ebhh : dbhh)[l*2048 + j];
    }
}

// ---------------- fused fp16 LSTM cell ----------------
// CTA tile: 128 batch x 128 gate-cols; K=1024 in 8 stages of 128 halves.
// 512 threads = 16 warps (4m x 4n), warp tile 32x32. ldmatrix.x4. 3-slot ring.
// Gate-aligned B layout: warp wn's four ni-tiles = gates i,f,g,o of h-cols
// [nh0+wn*8, +8) -> gate recombine entirely in registers (no smem epilogue).
#define ROWP 68
#define SLOTU (256*ROWP)          // 17408 u32 = 69632 B
#define SM_CELL (3*SLOTU*4)       // 208896 B

__global__ void __launch_bounds__(512, 1) cell_k(Diag dg)
{
    const Cell cl = dg.c[blockIdx.z];
    const __half* __restrict__ inp   = cl.inp;
    const __half* __restrict__ hprev = cl.hprev;
    const __half* __restrict__ W     = cl.W;
    const float*  __restrict__ bsum  = cl.bsum;
    float*        __restrict__ cbuf  = cl.cbuf;
    __half*       __restrict__ hout  = cl.hout;

    extern __shared__ unsigned smbuf[];
    const uint32_t sb = (uint32_t)__cvta_generic_to_shared(smbuf);

    const int tid = threadIdx.x;
    const int m0  = blockIdx.x * 128;
    const int nh0 = blockIdx.y * 32;
    const int warp = tid >> 5, lane = tid & 31;
    const int wm = warp & 3, wn = warp >> 2;     // 4m x 4n, warp tile 32x32
    const int gr = lane >> 2, ct = lane & 3;

    // bias preload: this thread's 2 h-cols for all 4 gates
    const int hhA = nh0 + wn*8 + 2*ct;           // even
    float bI[2], bF[2], bG[2], bO[2];
    bI[0] = bsum[       hhA]; bI[1] = bsum[       hhA + 1];
    bF[0] = bsum[ 512 + hhA]; bF[1] = bsum[ 512 + hhA + 1];
    bG[0] = bsum[1024 + hhA]; bG[1] = bsum[1024 + hhA + 1];
    bO[0] = bsum[1536 + hhA]; bO[1] = bsum[1536 + hhA + 1];

    float acc[2][4][4];
    #pragma unroll
    for (int i=0;i<2;i++)
        #pragma unroll
        for (int j=0;j<4;j++){
            acc[i][j][0]=0.f; acc[i][j][1]=0.f; acc[i][j][2]=0.f; acc[i][j][3]=0.f;
        }

    // ldmatrix lane-address offsets (bytes within slot)
    const uint32_t aOff = (uint32_t)((wm*32 + (lane & 15))*272 + ((lane >> 4) << 4));
    const uint32_t bOff = (uint32_t)((128 + wn*32 + ((lane & 7) | (((lane >> 4) & 1) << 3)))*272
                                     + (((lane >> 3) & 1) << 4));

    // per stage: A,B each 128 rows x 128 halves = 2048 16B-chunks -> 4+4 per thread
    auto load_stage = [&](int s){
        unsigned* slot = smbuf + (s % 3)*SLOTU;
        int kg = s*128;
        const __half* Asrc = (kg < 512) ? (inp + kg) : (hprev + (kg - 512));
        #pragma unroll
        for (int i = 0; i < 4; i++){
            int lin = i*512 + tid;            // 0..2047
            int r = lin >> 4, q = lin & 15;
            cp16(slot + r*ROWP + q*4, Asrc + (size_t)(m0 + r)*512 + q*8);
        }
        #pragma unroll
        for (int i = 0; i < 4; i++){
            int lin = i*512 + tid;
            int r = lin >> 4, q = lin & 15;
            // gate-aligned: row r -> gate (r>>3)&3, h-col (r>>5)*8 + (r&7)
            int jB = (((r >> 3) & 3) << 9) + nh0 + ((r >> 5) << 3) + (r & 7);
            cp16(slot + (128 + r)*ROWP + q*4, W + (size_t)jB*1024 + kg + q*8);
        }
        cp_commit();
    };

    load_stage(0); load_stage(1);

    #pragma unroll 1
    for (int s = 0; s < 8; s++){
        if (s < 7) cp_wait<1>();
        else       cp_wait<0>();
        __syncthreads();                       // stage s visible; slot (s-1)%3 consumed
        if (s < 6) load_stage(s+2);

        const uint32_t slot_b = sb + (uint32_t)(s % 3)*(SLOTU*4);

        #pragma unroll
        for (int kit = 0; kit < 8; kit++){
            unsigned af[2][4], bfr[2][4];
            #pragma unroll
            for (int mi = 0; mi < 2; mi++)
                ldsm4(af[mi], slot_b + aOff + (uint32_t)mi*(16*272) + kit*32);
            #pragma unroll
            for (int p = 0; p < 2; p++)
                ldsm4(bfr[p], slot_b + bOff + (uint32_t)p*(16*272) + kit*32);
            #pragma unroll
            for (int mi = 0; mi < 2; mi++)
                #pragma unroll
                for (int ni = 0; ni < 4; ni++)
                    mma16(acc[mi][ni], af[mi], &bfr[ni >> 1][(ni & 1) << 1]);
        }
    }

    // register-resident gate recombine: acc[mi][gate][j] all refer to same (m, hh)
    #pragma unroll
    for (int mi = 0; mi < 2; mi++){
        #pragma unroll
        for (int jr = 0; jr < 2; jr++){
            int m = m0 + wm*32 + mi*16 + gr + jr*8;
            size_t gx = (size_t)m*512 + hhA;
            float2 cc = *(const float2*)(cbuf + gx);
            float cv[2] = {cc.x, cc.y};
            float hn[2];
            #pragma unroll
            for (int jc = 0; jc < 2; jc++){
                int j = jr*2 + jc;
                float gi = acc[mi][0][j] + bI[jc];
                float gf = acc[mi][1][j] + bF[jc];
                float gg = acc[mi][2][j] + bG[jc];
                float go = acc[mi][3][j] + bO[jc];
                float c2 = sigm(gf)*cv[jc] + sigm(gi)*tanhf(gg);
                cv[jc] = c2;
                hn[jc] = sigm(go)*tanhf(c2);
            }
            *(float2*)(cbuf + gx) = make_float2(cv[0], cv[1]);
            __half2 h2v = __floats2half2_rn(hn[0], hn[1]);
            *(__half2*)(hout + gx) = h2v;
        }
    }
}

// ---------------- output projection (fp16 mma) ----------------
#define PROWP 20
#define PSLOTU ((64+128)*PROWP)
#define SM_PROJ (64*132*4)

__global__ void __launch_bounds__(128, 1) proj_k(const float* __restrict__ outb,
                                                 float* __restrict__ out)
{
    extern __shared__ unsigned smbuf[];
    float* sg = (float*)smbuf;

    const int tid = threadIdx.x;
    const int o0  = blockIdx.x * 128;
    const int b   = blockIdx.y;
    const int warp = tid >> 5, lane = tid & 31;
    const int wm = warp & 1, wn = warp >> 1;
    const int gr = lane >> 2, ct = lane & 3;

    const __half* Aglob = &g_dout[0][0] + (size_t)b*512;

    float acc[2][8][4];
    #pragma unroll
    for (int i=0;i<2;i++)
        #pragma unroll
        for (int j=0;j<8;j++){
            acc[i][j][0]=0.f; acc[i][j][1]=0.f; acc[i][j][2]=0.f; acc[i][j][3]=0.f;
        }

    auto load_stage = [&](int s){
        unsigned* slot = smbuf + (s & 1)*PSLOTU;
        int kg = s*32;
        #pragma unroll
        for (int i=0;i<6;i++){
            int lin = i*128 + tid;
            if (lin < 256){
                int r = lin >> 2, q = lin & 3;
                cp16(slot + r*PROWP + q*4, Aglob + (size_t)r*BH + kg + q*8);
            } else {
                int l2 = lin - 256; int r = l2 >> 2, q = l2 & 3;
                cp16(slot + (64 + r)*PROWP + q*4, g_Wout + (size_t)(o0 + r)*512 + kg + q*8);
            }
        }
        cp_commit();
    };

    load_stage(0);

    #pragma unroll 1
    for (int s = 0; s < 16; s++){
        if (s < 15){
            load_stage(s+1);
            cp_wait<1>();
        } else {
            cp_wait<0>();
        }
        __syncthreads();

        unsigned* A  = smbuf + (s & 1)*PSLOTU;
        unsigned* Bm = A + 64*PROWP;

        #pragma unroll
        for (int kit = 0; kit < 2; kit++){
            const int kk2 = kit*8;
            unsigned af[2][4], bf[8][2];
            #pragma unroll
            for (int mi=0;mi<2;mi++){
                int rb = wm*32 + mi*16;
                af[mi][0] = A[(rb+gr  )*PROWP + kk2 + ct    ];
                af[mi][1] = A[(rb+gr+8)*PROWP + kk2 + ct    ];
                af[mi][2] = A[(rb+gr  )*PROWP + kk2 + ct + 4];
                af[mi][3] = A[(rb+gr+8)*PROWP + kk2 + ct + 4];
            }
            #pragma unroll
            for (int ni=0;ni<8;ni++){
                int cb = wn*64 + ni*8;
                bf[ni][0] = Bm[(cb+gr)*PROWP + kk2 + ct    ];
                bf[ni][1] = Bm[(cb+gr)*PROWP + kk2 + ct + 4];
            }
            #pragma unroll
            for (int mi=0;mi<2;mi++)
                #pragma unroll
                for (int ni=0;ni<8;ni++)
                    mma16(acc[mi][ni], af[mi], bf[ni]);
        }
        __syncthreads();
    }

    #pragma unroll
    for (int mi=0;mi<2;mi++){
        #pragma unroll
        for (int ni=0;ni<8;ni++){
            int rb = wm*32 + mi*16 + gr;
            int cb = wn*64 + ni*8  + ct*2;
            sg[(size_t)rb*132 + cb]       = acc[mi][ni][0];
            sg[(size_t)rb*132 + cb + 1]   = acc[mi][ni][1];
            sg[(size_t)(rb+8)*132 + cb]   = acc[mi][ni][2];
            sg[(size_t)(rb+8)*132 + cb+1] = acc[mi][ni][3];
        }
    }
    __syncthreads();

    #pragma unroll 1
    for (int it = 0; it < 64; it++){
        int idx = it*128 + tid;
        int f = idx & 63, oc = idx >> 6;
        float v = sg[(size_t)f*132 + oc] + outb[o0 + oc];
        out[((size_t)b*512 + o0 + oc)*64 + f] = v;
    }
}

// ---------------- host ----------------
extern "C" void kernel_launch(void* const* d_in, const int* in_sizes, int n_in,
                              void* d_out, int out_size)
{
    (void)in_sizes; (void)n_in; (void)out_size;
    const float* seq  = (const float*)d_in[0];
    const float* eWih = (const float*)d_in[1];
    const float* eWhh = (const float*)d_in[2];
    const float* ebih = (const float*)d_in[3];
    const float* ebhh = (const float*)d_in[4];
    const float* dWih = (const float*)d_in[5];
    const float* dWhh = (const float*)d_in[6];
    const float* dbih = (const float*)d_in[7];
    const float* dbhh = (const float*)d_in[8];
    const float* oW   = (const float*)d_in[9];
    const float* ob   = (const float*)d_in[10];
    float* out = (float*)d_out;

    void *p_h, *p_c, *p_x, *p_dout, *p_W, *p_bs;
    cudaGetSymbolAddress(&p_h,    g_hbuf);
    cudaGetSymbolAddress(&p_c,    g_cbuf);
    cudaGetSymbolAddress(&p_x,    g_x);
    cudaGetSymbolAddress(&p_dout, g_dout);
    cudaGetSymbolAddress(&p_W,    g_W);
    cudaGetSymbolAddress(&p_bs,   g_bsum);

    __half* hb = (__half*)p_h;
    float*  cb = (float*)p_c;
    __half* xb = (__half*)p_x;
    __half* db = (__half*)p_dout;
    __half* Wb = (__half*)p_W;
    float*  bb = (float*)p_bs;

    cudaFuncSetAttribute(cell_k, cudaFuncAttributeMaxDynamicSharedMemorySize, SM_CELL);
    cudaFuncSetAttribute(proj_k, cudaFuncAttributeMaxDynamicSharedMemorySize, SM_PROJ);

    cudaMemsetAsync(hb, 0, sizeof(__half)*3*BH, 0);
    cudaMemsetAsync(cb, 0, sizeof(float)*3*BH, 0);

    transpose_k<<<dim3(16,2,1024), dim3(32,32)>>>(seq);
    {
        long long tot = 6LL*2048*1024 + 512LL*512 + 6LL*2048;
        int blocks = (int)((tot + 255)/256);
        wconv_k<<<blocks, 256>>>(eWih,eWhh,ebih,ebhh,dWih,dWhh,dbih,dbhh,oW);
    }

    auto enc_cell = [&](int t, int l) -> Cell {
        int cur = t & 1, nxt = cur ^ 1;
        Cell c;
        c.inp   = (l == 0) ? (xb + (size_t)t*BH) : (hb + ((size_t)nxt*3 + (l-1))*BH);
        c.hprev = hb + ((size_t)cur*3 + l)*BH;
        c.W     = Wb + (size_t)l*Gv*1024;
        c.bsum  = bb + (size_t)l*Gv;
        c.cbuf  = cb + (size_t)l*BH;
        c.hout  = hb + ((size_t)nxt*3 + l)*BH;
        return c;
    };

    // encoder: wavefront diagonals w = t + l
    for (int w = 0; w <= 64; w++){
        Diag dg; int cnt = 0;
        for (int l = 0; l < 3; l++){
            int t = w - l;
            if (t < 0 || t > 62) continue;
            dg.c[cnt++] = enc_cell(t, l);
        }
        if (cnt == 0) continue;
        for (int k = cnt; k < 3; k++) dg.c[k] = dg.c[0];
        cell_k<<<dim3(8,16,cnt), 512, SM_CELL>>>(dg);
    }

    // decoder: 64 steps x 3 layers, strictly serial
    for (int d = 0; d < 64; d++){
        int cur = (63 + d) & 1, nxt = cur ^ 1;
        const __half* in0 = (d == 0) ? (xb + (size_t)62*BH) : (db + (size_t)(d-1)*BH);

        Diag dg;
        dg.c[0] = { in0, hb + ((size_t)cur*3 + 0)*BH, Wb + (size_t)3*Gv*1024,
                    bb + (size_t)3*Gv, cb + 0, hb + ((size_t)nxt*3 + 0)*BH };
        dg.c[1] = dg.c[0]; dg.c[2] = dg.c[0];
        cell_k<<<dim3(8,16,1), 512, SM_CELL>>>(dg);

        dg.c[0] = { hb + ((size_t)nxt*3 + 0)*BH, hb + ((size_t)cur*3 + 1)*BH,
                    Wb + (size_t)4*Gv*1024, bb + (size_t)4*Gv,
                    cb + (size_t)1*BH, hb + ((size_t)nxt*3 + 1)*BH };
        dg.c[1] = dg.c[0]; dg.c[2] = dg.c[0];
        cell_k<<<dim3(8,16,1), 512, SM_CELL>>>(dg);

        const __half* h2prev = (d == 0) ? (hb + ((size_t)cur*3 + 2)*BH)
                                        : (db + (size_t)(d-1)*BH);
        dg.c[0] = { hb + ((size_t)nxt*3 + 1)*BH, h2prev,
                    Wb + (size_t)5*Gv*1024, bb + (size_t)5*Gv,
                    cb + (size_t)2*BH, db + (size_t)d*BH };
        dg.c[1] = dg.c[0]; dg.c[2] = dg.c[0];
        cell_k<<<dim3(8,16,1), 512, SM_CELL>>>(dg);
    }

    proj_k<<<dim3(4,1024), 128, SM_PROJ>>>(ob, out);
}

// round 16
// speedup vs baseline: 1.5446x; 1.5446x over previous
#include <cuda_runtime.h>
#include <cuda_fp16.h>
#include <math.h>
#include <stdint.h>

#define Bv 1024
#define Hv 512
#define Gv 2048
#define Tv 64
#define FUT 64
#define BH (Bv*Hv)

// ---------------- static device scratch ----------------
__device__ __half  g_hbuf[2][3][BH];
__device__ float   g_cbuf[3][BH];
__device__ __half  g_x[Tv][BH];
__device__ __half  g_dout[FUT][BH];
__device__ __half  g_W[6][Gv*1024];
__device__ float   g_bsum[6][Gv];
__device__ __half  g_Wout[Hv*Hv];

struct Cell {
    const __half* inp; const __half* hprev; const __half* W;
    const float* bsum; float* cbuf; __half* hout;
};
struct Diag { Cell c[3]; };

// ---------------- helpers ----------------
__device__ __forceinline__ void cp16(void* s, const void* g){
    unsigned sa = (unsigned)__cvta_generic_to_shared(s);
    asm volatile("cp.async.cg.shared.global [%0], [%1], 16;\n" :: "r"(sa), "l"(g));
}
__device__ __forceinline__ void cp_commit(){
    asm volatile("cp.async.commit_group;\n" ::: "memory");
}
template<int N> __device__ __forceinline__ void cp_wait(){
    asm volatile("cp.async.wait_group %0;\n" :: "n"(N) : "memory");
}
__device__ __forceinline__ void mma16(float* c, const unsigned* a, const unsigned* b){
    asm volatile("mma.sync.aligned.m16n8k16.row.col.f32.f16.f16.f32 "
        "{%0,%1,%2,%3}, {%4,%5,%6,%7}, {%8,%9}, {%0,%1,%2,%3};\n"
        : "+f"(c[0]), "+f"(c[1]), "+f"(c[2]), "+f"(c[3])
        : "r"(a[0]), "r"(a[1]), "r"(a[2]), "r"(a[3]), "r"(b[0]), "r"(b[1]));
}
__device__ __forceinline__ void ldsm4(unsigned* r, uint32_t a){
    asm volatile("ldmatrix.sync.aligned.m8n8.x4.shared.b16 {%0,%1,%2,%3}, [%4];"
        : "=r"(r[0]), "=r"(r[1]), "=r"(r[2]), "=r"(r[3]) : "r"(a));
}
__device__ __forceinline__ float sigm(float x){ return 1.f/(1.f + __expf(-x)); }

// ---------------- prep kernels ----------------
__global__ void transpose_k(const float* __restrict__ in){
    __shared__ float tile[32][33];
    int b = blockIdx.z;
    int h0 = blockIdx.x*32, t0 = blockIdx.y*32;
    int tx = threadIdx.x, ty = threadIdx.y;
    tile[ty][tx] = in[((size_t)b*Hv + h0 + ty)*Tv + t0 + tx];
    __syncthreads();
    g_x[t0+ty][(size_t)b*Hv + h0 + tx] = __float2half(tile[tx][ty]);
}

__global__ void wconv_k(const float* __restrict__ eWih, const float* __restrict__ eWhh,
                        const float* __restrict__ ebih, const float* __restrict__ ebhh,
                        const float* __restrict__ dWih, const float* __restrict__ dWhh,
                        const float* __restrict__ dbih, const float* __restrict__ dbhh,
                        const float* __restrict__ oW){
    long long idx = (long long)blockIdx.x*256 + threadIdx.x;
    const long long N1 = 6LL*2048*1024;
    const long long N2 = 512LL*512;
    const long long N3 = 6LL*2048;
    if (idx < N1){
        int L   = (int)(idx >> 21);
        int rem = (int)(idx & ((1u<<21)-1));
        int j = rem >> 10, k = rem & 1023;
        int l = (L < 3) ? L : L - 3;
        const float* Wih = (L < 3) ? eWih : dWih;
        const float* Whh = (L < 3) ? eWhh : dWhh;
        float v = (k < 512) ? Wih[((size_t)l*2048 + j)*512 + k]
                            : Whh[((size_t)l*2048 + j)*512 + k - 512];
        ((__half*)g_W)[idx] = __float2half(v);
    } else if (idx < N1 + N2){
        int i2 = (int)(idx - N1);
        ((__half*)g_Wout)[i2] = __float2half(oW[i2]);
    } else if (idx < N1 + N2 + N3){
        int i3 = (int)(idx - N1 - N2);
        int L = i3 >> 11, j = i3 & 2047;
        int l = (L < 3) ? L : L - 3;
        ((float*)g_bsum)[i3] = ((L < 3) ? ebih : dbih)[l*2048 + j]
                             + ((L < 3) ? ebhh : dbhh)[l*2048 + j];
    }
}

// ---------------- fused fp16 LSTM cell ----------------
// CTA tile: 128 batch x 128 gate-cols; K=1024 in 8 stages of 128 halves.
// 512 threads = 16 warps (4m x 4n), warp tile 32x32. ldmatrix.x4. 3-slot ring.
// Gate-aligned B layout: warp wn's four ni-tiles = gates i,f,g,o of h-cols
// [nh0+wn*8, +8) -> gate recombine entirely in registers (no smem epilogue).
#define ROWP 68
#define SLOTU (256*ROWP)          // 17408 u32 = 69632 B
#define SM_CELL (3*SLOTU*4)       // 208896 B

__global__ void __launch_bounds__(512, 1) cell_k(Diag dg)
{
    const Cell cl = dg.c[blockIdx.z];
    const __half* __restrict__ inp   = cl.inp;
    const __half* __restrict__ hprev = cl.hprev;
    const __half* __restrict__ W     = cl.W;
    const float*  __restrict__ bsum  = cl.bsum;
    float*        __restrict__ cbuf  = cl.cbuf;
    __half*       __restrict__ hout  = cl.hout;

    extern __shared__ unsigned smbuf[];
    const uint32_t sb = (uint32_t)__cvta_generic_to_shared(smbuf);

    const int tid = threadIdx.x;
    const int m0  = blockIdx.x * 128;
    const int nh0 = blockIdx.y * 32;
    const int warp = tid >> 5, lane = tid & 31;
    const int wm = warp & 3, wn = warp >> 2;     // 4m x 4n, warp tile 32x32
    const int gr = lane >> 2, ct = lane & 3;

    // bias preload: this thread's 2 h-cols for all 4 gates
    const int hhA = nh0 + wn*8 + 2*ct;           // even
    float bI[2], bF[2], bG[2], bO[2];
    bI[0] = bsum[       hhA]; bI[1] = bsum[       hhA + 1];
    bF[0] = bsum[ 512 + hhA]; bF[1] = bsum[ 512 + hhA + 1];
    bG[0] = bsum[1024 + hhA]; bG[1] = bsum[1024 + hhA + 1];
    bO[0] = bsum[1536 + hhA]; bO[1] = bsum[1536 + hhA + 1];

    float acc[2][4][4];
    #pragma unroll
    for (int i=0;i<2;i++)
        #pragma unroll
        for (int j=0;j<4;j++){
            acc[i][j][0]=0.f; acc[i][j][1]=0.f; acc[i][j][2]=0.f; acc[i][j][3]=0.f;
        }

    // ldmatrix lane-address offsets (bytes within slot)
    const uint32_t aOff = (uint32_t)((wm*32 + (lane & 15))*272 + ((lane >> 4) << 4));
    const uint32_t bOff = (uint32_t)((128 + wn*32 + ((lane & 7) | (((lane >> 4) & 1) << 3)))*272
                                     + (((lane >> 3) & 1) << 4));

    // per stage: A,B each 128 rows x 128 halves = 2048 16B-chunks -> 4+4 per thread
    auto load_stage = [&](int s){
        unsigned* slot = smbuf + (s % 3)*SLOTU;
        int kg = s*128;
        const __half* Asrc = (kg < 512) ? (inp + kg) : (hprev + (kg - 512));
        #pragma unroll
        for (int i = 0; i < 4; i++){
            int lin = i*512 + tid;            // 0..2047
            int r = lin >> 4, q = lin & 15;
            cp16(slot + r*ROWP + q*4, Asrc + (size_t)(m0 + r)*512 + q*8);
        }
        #pragma unroll
        for (int i = 0; i < 4; i++){
            int lin = i*512 + tid;
            int r = lin >> 4, q = lin & 15;
            // gate-aligned: row r -> gate (r>>3)&3, h-col (r>>5)*8 + (r&7)
            int jB = (((r >> 3) & 3) << 9) + nh0 + ((r >> 5) << 3) + (r & 7);
            cp16(slot + (128 + r)*ROWP + q*4, W + (size_t)jB*1024 + kg + q*8);
        }
        cp_commit();
    };

    load_stage(0); load_stage(1);

    #pragma unroll 1
    for (int s = 0; s < 8; s++){
        if (s < 7) cp_wait<1>();
        else       cp_wait<0>();
        __syncthreads();                       // stage s visible; slot (s-1)%3 consumed
        if (s < 6) load_stage(s+2);

        const uint32_t slot_b = sb + (uint32_t)(s % 3)*(SLOTU*4);

        #pragma unroll
        for (int kit = 0; kit < 8; kit++){
            unsigned af[2][4], bfr[2][4];
            #pragma unroll
            for (int mi = 0; mi < 2; mi++)
                ldsm4(af[mi], slot_b + aOff + (uint32_t)mi*(16*272) + kit*32);
            #pragma unroll
            for (int p = 0; p < 2; p++)
                ldsm4(bfr[p], slot_b + bOff + (uint32_t)p*(16*272) + kit*32);
            #pragma unroll
            for (int mi = 0; mi < 2; mi++)
                #pragma unroll
                for (int ni = 0; ni < 4; ni++)
                    mma16(acc[mi][ni], af[mi], &bfr[ni >> 1][(ni & 1) << 1]);
        }
    }

    // register-resident gate recombine: acc[mi][gate][j] all refer to same (m, hh)
    #pragma unroll
    for (int mi = 0; mi < 2; mi++){
        #pragma unroll
        for (int jr = 0; jr < 2; jr++){
            int m = m0 + wm*32 + mi*16 + gr + jr*8;
            size_t gx = (size_t)m*512 + hhA;
            float2 cc = *(const float2*)(cbuf + gx);
            float cv[2] = {cc.x, cc.y};
            float hn[2];
            #pragma unroll
            for (int jc = 0; jc < 2; jc++){
                int j = jr*2 + jc;
                float gi = acc[mi][0][j] + bI[jc];
                float gf = acc[mi][1][j] + bF[jc];
                float gg = acc[mi][2][j] + bG[jc];
                float go = acc[mi][3][j] + bO[jc];
                float c2 = sigm(gf)*cv[jc] + sigm(gi)*tanhf(gg);
                cv[jc] = c2;
                hn[jc] = sigm(go)*tanhf(c2);
            }
            *(float2*)(cbuf + gx) = make_float2(cv[0], cv[1]);
            __half2 h2v = __floats2half2_rn(hn[0], hn[1]);
            *(__half2*)(hout + gx) = h2v;
        }
    }
}

// ---------------- output projection (fp16 mma) ----------------
#define PROWP 20
#define PSLOTU ((64+128)*PROWP)
#define SM_PROJ (64*132*4)

__global__ void __launch_bounds__(128, 1) proj_k(const float* __restrict__ outb,
                                                 float* __restrict__ out)
{
    extern __shared__ unsigned smbuf[];
    float* sg = (float*)smbuf;

    const int tid = threadIdx.x;
    const int o0  = blockIdx.x * 128;
    const int b   = blockIdx.y;
    const int warp = tid >> 5, lane = tid & 31;
    const int wm = warp & 1, wn = warp >> 1;
    const int gr = lane >> 2, ct = lane & 3;

    const __half* Aglob = &g_dout[0][0] + (size_t)b*512;

    float acc[2][8][4];
    #pragma unroll
    for (int i=0;i<2;i++)
        #pragma unroll
        for (int j=0;j<8;j++){
            acc[i][j][0]=0.f; acc[i][j][1]=0.f; acc[i][j][2]=0.f; acc[i][j][3]=0.f;
        }

    auto load_stage = [&](int s){
        unsigned* slot = smbuf + (s & 1)*PSLOTU;
        int kg = s*32;
        #pragma unroll
        for (int i=0;i<6;i++){
            int lin = i*128 + tid;
            if (lin < 256){
                int r = lin >> 2, q = lin & 3;
                cp16(slot + r*PROWP + q*4, Aglob + (size_t)r*BH + kg + q*8);
            } else {
                int l2 = lin - 256; int r = l2 >> 2, q = l2 & 3;
                cp16(slot + (64 + r)*PROWP + q*4, g_Wout + (size_t)(o0 + r)*512 + kg + q*8);
            }
        }
        cp_commit();
    };

    load_stage(0);

    #pragma unroll 1
    for (int s = 0; s < 16; s++){
        if (s < 15){
            load_stage(s+1);
            cp_wait<1>();
        } else {
            cp_wait<0>();
        }
        __syncthreads();

        unsigned* A  = smbuf + (s & 1)*PSLOTU;
        unsigned* Bm = A + 64*PROWP;

        #pragma unroll
        for (int kit = 0; kit < 2; kit++){
            const int kk2 = kit*8;
            unsigned af[2][4], bf[8][2];
            #pragma unroll
            for (int mi=0;mi<2;mi++){
                int rb = wm*32 + mi*16;
                af[mi][0] = A[(rb+gr  )*PROWP + kk2 + ct    ];
                af[mi][1] = A[(rb+gr+8)*PROWP + kk2 + ct    ];
                af[mi][2] = A[(rb+gr  )*PROWP + kk2 + ct + 4];
                af[mi][3] = A[(rb+gr+8)*PROWP + kk2 + ct + 4];
            }
            #pragma unroll
            for (int ni=0;ni<8;ni++){
                int cb = wn*64 + ni*8;
                bf[ni][0] = Bm[(cb+gr)*PROWP + kk2 + ct    ];
                bf[ni][1] = Bm[(cb+gr)*PROWP + kk2 + ct + 4];
            }
            #pragma unroll
            for (int mi=0;mi<2;mi++)
                #pragma unroll
                for (int ni=0;ni<8;ni++)
                    mma16(acc[mi][ni], af[mi], bf[ni]);
        }
        __syncthreads();
    }

    #pragma unroll
    for (int mi=0;mi<2;mi++){
        #pragma unroll
        for (int ni=0;ni<8;ni++){
            int rb = wm*32 + mi*16 + gr;
            int cb = wn*64 + ni*8  + ct*2;
            sg[(size_t)rb*132 + cb]       = acc[mi][ni][0];
            sg[(size_t)rb*132 + cb + 1]   = acc[mi][ni][1];
            sg[(size_t)(rb+8)*132 + cb]   = acc[mi][ni][2];
            sg[(size_t)(rb+8)*132 + cb+1] = acc[mi][ni][3];
        }
    }
    __syncthreads();

    #pragma unroll 1
    for (int it = 0; it < 64; it++){
        int idx = it*128 + tid;
        int f = idx & 63, oc = idx >> 6;
        float v = sg[(size_t)f*132 + oc] + outb[o0 + oc];
        out[((size_t)b*512 + o0 + oc)*64 + f] = v;
    }
}

// ---------------- host ----------------
extern "C" void kernel_launch(void* const* d_in, const int* in_sizes, int n_in,
                              void* d_out, int out_size)
{
    (void)in_sizes; (void)n_in; (void)out_size;
    const float* seq  = (const float*)d_in[0];
    const float* eWih = (const float*)d_in[1];
    const float* eWhh = (const float*)d_in[2];
    const float* ebih = (const float*)d_in[3];
    const float* ebhh = (const float*)d_in[4];
    const float* dWih = (const float*)d_in[5];
    const float* dWhh = (const float*)d_in[6];
    const float* dbih = (const float*)d_in[7];
    const float* dbhh = (const float*)d_in[8];
    const float* oW   = (const float*)d_in[9];
    const float* ob   = (const float*)d_in[10];
    float* out = (float*)d_out;

    void *p_h, *p_c, *p_x, *p_dout, *p_W, *p_bs;
    cudaGetSymbolAddress(&p_h,    g_hbuf);
    cudaGetSymbolAddress(&p_c,    g_cbuf);
    cudaGetSymbolAddress(&p_x,    g_x);
    cudaGetSymbolAddress(&p_dout, g_dout);
    cudaGetSymbolAddress(&p_W,    g_W);
    cudaGetSymbolAddress(&p_bs,   g_bsum);

    __half* hb = (__half*)p_h;
    float*  cb = (float*)p_c;
    __half* xb = (__half*)p_x;
    __half* db = (__half*)p_dout;
    __half* Wb = (__half*)p_W;
    float*  bb = (float*)p_bs;

    cudaFuncSetAttribute(cell_k, cudaFuncAttributeMaxDynamicSharedMemorySize, SM_CELL);
    cudaFuncSetAttribute(proj_k, cudaFuncAttributeMaxDynamicSharedMemorySize, SM_PROJ);

    cudaMemsetAsync(hb, 0, sizeof(__half)*3*BH, 0);
    cudaMemsetAsync(cb, 0, sizeof(float)*3*BH, 0);

    transpose_k<<<dim3(16,2,1024), dim3(32,32)>>>(seq);
    {
        long long tot = 6LL*2048*1024 + 512LL*512 + 6LL*2048;
        int blocks = (int)((tot + 255)/256);
        wconv_k<<<blocks, 256>>>(eWih,eWhh,ebih,ebhh,dWih,dWhh,dbih,dbhh,oW);
    }

    auto enc_cell = [&](int t, int l) -> Cell {
        int cur = t & 1, nxt = cur ^ 1;
        Cell c;
        c.inp   = (l == 0) ? (xb + (size_t)t*BH) : (hb + ((size_t)nxt*3 + (l-1))*BH);
        c.hprev = hb + ((size_t)cur*3 + l)*BH;
        c.W     = Wb + (size_t)l*Gv*1024;
        c.bsum  = bb + (size_t)l*Gv;
        c.cbuf  = cb + (size_t)l*BH;
        c.hout  = hb + ((size_t)nxt*3 + l)*BH;
        return c;
    };

    // encoder: wavefront diagonals w = t + l
    for (int w = 0; w <= 64; w++){
        Diag dg; int cnt = 0;
        for (int l = 0; l < 3; l++){
            int t = w - l;
            if (t < 0 || t > 62) continue;
            dg.c[cnt++] = enc_cell(t, l);
        }
        if (cnt == 0) continue;
        for (int k = cnt; k < 3; k++) dg.c[k] = dg.c[0];
        cell_k<<<dim3(8,16,cnt), 512, SM_CELL>>>(dg);
    }

    // decoder: 64 steps x 3 layers, strictly serial
    for (int d = 0; d < 64; d++){
        int cur = (63 + d) & 1, nxt = cur ^ 1;
        const __half* in0 = (d == 0) ? (xb + (size_t)62*BH) : (db + (size_t)(d-1)*BH);

        Diag dg;
        dg.c[0] = { in0, hb + ((size_t)cur*3 + 0)*BH, Wb + (size_t)3*Gv*1024,
                    bb + (size_t)3*Gv, cb + 0, hb + ((size_t)nxt*3 + 0)*BH };
        dg.c[1] = dg.c[0]; dg.c[2] = dg.c[0];
        cell_k<<<dim3(8,16,1), 512, SM_CELL>>>(dg);

        dg.c[0] = { hb + ((size_t)nxt*3 + 0)*BH, hb + ((size_t)cur*3 + 1)*BH,
                    Wb + (size_t)4*Gv*1024, bb + (size_t)4*Gv,
                    cb + (size_t)1*BH, hb + ((size_t)nxt*3 + 1)*BH };
        dg.c[1] = dg.c[0]; dg.c[2] = dg.c[0];
        cell_k<<<dim3(8,16,1), 512, SM_CELL>>>(dg);

        const __half* h2prev = (d == 0) ? (hb + ((size_t)cur*3 + 2)*BH)
                                        : (db + (size_t)(d-1)*BH);
        dg.c[0] = { hb + ((size_t)nxt*3 + 1)*BH, h2prev,
                    Wb + (size_t)5*Gv*1024, bb + (size_t)5*Gv,
                    cb + (size_t)2*BH, db + (size_t)d*BH };
        dg.c[1] = dg.c[0]; dg.c[2] = dg.c[0];
        cell_k<<<dim3(8,16,1), 512, SM_CELL>>>(dg);
    }

    proj_k<<<dim3(4,1024), 128, SM_PROJ>>>(ob, out);
}